// round 1
// baseline (speedup 1.0000x reference)
#include <cuda_runtime.h>
#include <math.h>
#include <stdint.h>

// Problem constants
#define M_TOTAL 32768   // BATCH * SEQ
#define E_DIM   512     // embed dim (output cols, also x row stride)
#define F_DIM   2048    // ffn dim (K of big GEMM)
#define NQ      8       // n_qubits

// Tiling
#define BM 128
#define BN 128
#define BK 32
#define THREADS 256
#define K_ITERS (F_DIM / BK)   // 64

__device__ __forceinline__ float to_tf32(float v) {
    uint32_t b;
    asm volatile("cvt.rna.tf32.f32 %0, %1;\n" : "=r"(b) : "f"(v));
    return __uint_as_float(b);
}

__device__ __forceinline__ void mma_tf32(float* c, const float4& a, const float2& b) {
    asm volatile(
        "mma.sync.aligned.m16n8k8.row.col.f32.tf32.tf32.f32 "
        "{%0,%1,%2,%3}, {%4,%5,%6,%7}, {%8,%9}, {%0,%1,%2,%3};\n"
        : "+f"(c[0]), "+f"(c[1]), "+f"(c[2]), "+f"(c[3])
        : "r"(__float_as_uint(a.x)), "r"(__float_as_uint(a.y)),
          "r"(__float_as_uint(a.z)), "r"(__float_as_uint(a.w)),
          "r"(__float_as_uint(b.x)), "r"(__float_as_uint(b.y)));
}

__device__ __forceinline__ float dot8(const float4& qa, const float4& qb,
                                      const float4& wa, const float4& wb) {
    float s = qa.x * wa.x;
    s = fmaf(qa.y, wa.y, s);
    s = fmaf(qa.z, wa.z, s);
    s = fmaf(qa.w, wa.w, s);
    s = fmaf(qb.x, wb.x, s);
    s = fmaf(qb.y, wb.y, s);
    s = fmaf(qb.z, wb.z, s);
    s = fmaf(qb.w, wb.w, s);
    return s;
}

__global__ void __launch_bounds__(THREADS, 2)
ffq_kernel(const float* __restrict__ x,
           const float* __restrict__ theta,
           const float* __restrict__ W1,
           const float* __restrict__ W2,
           float* __restrict__ out)
{
    // Smem layout (all padded/fragment-ordered for conflict-free access)
    __shared__ float sQ[BM * 12];          // q[m*12 + j], j<8 (stride 12 -> conflict-free)
    __shared__ float sW1[2][BK * 12];      // W1 chunk double buffer, row k -> 8 floats, stride 12
    __shared__ float sH[32 * 128];         // A frags: ((tm*4+k8)*32 + lane)*4 + elem  (tm 0..7, k8 0..3)
    __shared__ float sB[64 * 64];          // B frags: ((tn*4+k8)*32 + lane)*2 + elem  (tn 0..15)

    const int tid  = threadIdx.x;
    const int warp = tid >> 5;
    const int lane = tid & 31;
    const int wm = warp >> 2;     // 0..1  (M direction, 64 rows each)
    const int wn = warp & 3;      // 0..3  (N direction, 32 cols each)

    const int bid = blockIdx.x;
    const int mt = bid >> 2;      // 256 m-tiles
    const int nt = bid & 3;       // 4 n-tiles
    const int m0 = mt * BM;
    const int n0 = nt * BN;

    // ---- q = cos(2*x[:, :8] + theta) for this CTA's 128 rows ----
    if (tid < BM) {
        const float* xr = x + (size_t)(m0 + tid) * E_DIM;
        float4 x0 = *(const float4*)xr;
        float4 x1 = *(const float4*)(xr + 4);
        float th[8];
        #pragma unroll
        for (int j = 0; j < 8; ++j) th[j] = __ldg(theta + j);
        float* qr = sQ + tid * 12;
        qr[0] = cosf(2.0f * x0.x + th[0]);
        qr[1] = cosf(2.0f * x0.y + th[1]);
        qr[2] = cosf(2.0f * x0.z + th[2]);
        qr[3] = cosf(2.0f * x0.w + th[3]);
        qr[4] = cosf(2.0f * x1.x + th[4]);
        qr[5] = cosf(2.0f * x1.y + th[5]);
        qr[6] = cosf(2.0f * x1.z + th[6]);
        qr[7] = cosf(2.0f * x1.w + th[7]);
    }
    // ---- stage W1 chunk 0 ----
    if (tid < 64) {
        int r = tid >> 1, h = tid & 1;
        float4 v = *(const float4*)(W1 + (size_t)r * NQ + h * 4);
        float* d = sW1[0] + r * 12 + h * 4;
        d[0] = v.x; d[1] = v.y; d[2] = v.z; d[3] = v.w;
    }
    __syncthreads();

    float acc[4][4][4];
    #pragma unroll
    for (int i = 0; i < 4; ++i)
        #pragma unroll
        for (int j = 0; j < 4; ++j)
            #pragma unroll
            for (int e = 0; e < 4; ++e) acc[i][j][e] = 0.0f;

    for (int it = 0; it < K_ITERS; ++it) {
        const int kk = it * BK;

        // Prefetch W2 chunk into regs (L2-resident after wave 1)
        float4 w2r[4];
        {
            const int erow = (tid >> 3);            // 0..31
            const int kcol = (tid & 7) << 2;        // 0,4,...,28
            #pragma unroll
            for (int p = 0; p < 4; ++p) {
                int e = n0 + p * 32 + erow;
                w2r[p] = *(const float4*)(W2 + (size_t)e * F_DIM + kk + kcol);
            }
        }
        // Prefetch next W1 chunk into regs
        float4 w1r = make_float4(0.f, 0.f, 0.f, 0.f);
        if (it + 1 < K_ITERS && tid < 64) {
            int r = tid >> 1, h = tid & 1;
            w1r = *(const float4*)(W1 + (size_t)(kk + 32 + r) * NQ + h * 4);
        }

        __syncthreads();  // (A) previous MMA pass done reading sH / sB

        // Store W2 chunk into B-fragment layout (tf32-rounded)
        {
            const int nloc = (tid >> 3);            // combined below with p
            const int kloc = (tid & 7) << 2;        // multiple of 4
            const int k8   = kloc >> 3;
            const int elem = (kloc >> 2) & 1;
            #pragma unroll
            for (int p = 0; p < 4; ++p) {
                int n_ = p * 32 + nloc;             // 0..127
                int tn = n_ >> 3;
                int lw = ((n_ & 7) << 2);           // + (kloc&3)==0
                float* d = sB + (size_t)((tn * 4 + k8) * 32 + lw) * 2 + elem;
                d[0] = to_tf32(w2r[p].x);
                d[2] = to_tf32(w2r[p].y);
                d[4] = to_tf32(w2r[p].z);
                d[6] = to_tf32(w2r[p].w);
            }
        }
        // Store next W1 chunk
        if (it + 1 < K_ITERS && tid < 64) {
            int r = tid >> 1, h = tid & 1;
            float* d = sW1[(it + 1) & 1] + r * 12 + h * 4;
            d[0] = w1r.x; d[1] = w1r.y; d[2] = w1r.z; d[3] = w1r.w;
        }

        // ---- H producer: warp w builds tiles (tm=w, k8=0..3) directly as A-fragments ----
        {
            const float* w1b = sW1[it & 1];
            const int m_lo = (warp << 4) + (lane >> 2);  // tm = warp
            const int kq   = lane & 3;
            const float* q0 = sQ + m_lo * 12;
            const float* q1 = sQ + (m_lo + 8) * 12;
            float4 qa0 = *(const float4*)q0;
            float4 qa1 = *(const float4*)(q0 + 4);
            float4 qb0 = *(const float4*)q1;
            float4 qb1 = *(const float4*)(q1 + 4);
            #pragma unroll
            for (int k8 = 0; k8 < 4; ++k8) {
                const int kA = (k8 << 3) + kq;
                const float* wA = w1b + kA * 12;
                const float* wB = w1b + (kA + 4) * 12;
                float4 wa0 = *(const float4*)wA;
                float4 wa1 = *(const float4*)(wA + 4);
                float4 wb0 = *(const float4*)wB;
                float4 wb1 = *(const float4*)(wB + 4);
                float h00 = fmaxf(dot8(qa0, qa1, wa0, wa1), 0.0f);  // (m,   k)
                float h10 = fmaxf(dot8(qb0, qb1, wa0, wa1), 0.0f);  // (m+8, k)
                float h01 = fmaxf(dot8(qa0, qa1, wb0, wb1), 0.0f);  // (m,   k+4)
                float h11 = fmaxf(dot8(qb0, qb1, wb0, wb1), 0.0f);  // (m+8, k+4)
                float4 frag = make_float4(to_tf32(h00), to_tf32(h10),
                                          to_tf32(h01), to_tf32(h11));
                *(float4*)(sH + (size_t)((warp * 4 + k8) * 32 + lane) * 4) = frag;
            }
        }

        __syncthreads();  // (B) sH / sB ready

        // ---- MMA consumer: warp tile 64(M) x 32(N) ----
        #pragma unroll
        for (int k8 = 0; k8 < 4; ++k8) {
            float4 a[4];
            #pragma unroll
            for (int im = 0; im < 4; ++im) {
                int tm = wm * 4 + im;
                a[im] = *(const float4*)(sH + (size_t)((tm * 4 + k8) * 32 + lane) * 4);
            }
            float2 b[4];
            #pragma unroll
            for (int jn = 0; jn < 4; ++jn) {
                int tn = wn * 4 + jn;
                b[jn] = *(const float2*)(sB + (size_t)((tn * 4 + k8) * 32 + lane) * 2);
            }
            #pragma unroll
            for (int im = 0; im < 4; ++im)
                #pragma unroll
                for (int jn = 0; jn < 4; ++jn)
                    mma_tf32(acc[im][jn], a[im], b[jn]);
        }
    }

    // ---- epilogue: fp32 accumulators -> global ----
    const int g  = lane >> 2;
    const int tq = lane & 3;
    #pragma unroll
    for (int im = 0; im < 4; ++im) {
        int mrow = m0 + wm * 64 + im * 16 + g;
        #pragma unroll
        for (int jn = 0; jn < 4; ++jn) {
            int col = n0 + wn * 32 + jn * 8 + 2 * tq;
            float* o0 = out + (size_t)mrow * E_DIM + col;
            float* o1 = out + (size_t)(mrow + 8) * E_DIM + col;
            *(float2*)o0 = make_float2(acc[im][jn][0], acc[im][jn][1]);
            *(float2*)o1 = make_float2(acc[im][jn][2], acc[im][jn][3]);
        }
    }
}

extern "C" void kernel_launch(void* const* d_in, const int* in_sizes, int n_in,
                              void* d_out, int out_size) {
    const float* x     = (const float*)d_in[0];
    const float* theta = (const float*)d_in[1];
    const float* W1    = (const float*)d_in[2];
    const float* W2    = (const float*)d_in[3];
    float* out = (float*)d_out;

    dim3 grid((M_TOTAL / BM) * (E_DIM / BN));  // 256 * 4 = 1024 CTAs
    ffq_kernel<<<grid, THREADS>>>(x, theta, W1, W2, out);
}

// round 4
// speedup vs baseline: 1.0608x; 1.0608x over previous
#include <cuda_runtime.h>
#include <cuda_fp16.h>
#include <math.h>
#include <stdint.h>

#define M_TOTAL 32768
#define E_DIM   512
#define F_DIM   2048

#define BM 256
#define BN 128
#define BK 32
#define THREADS 512
#define K_ITERS 64

// smem offsets (relative to 1024-aligned base)
#define SW1  0           // W1 fp32 [2048][8]   = 65536 B
#define SA0  65536       // A (H fp16) [256][32] dbl: 2 x 16384
#define SAB  16384
#define SB0  98304       // B (W2 fp16) [128][32] dbl: 2 x 8192
#define SBB  8192
#define SQ   114688      // q fp32 [256][8] = 8192
#define SMEM_BYTES (122880 + 1024)

// fp16 copy of W2 (E x F), stored as uint4 for 16B-aligned vector access
__device__ uint4 g_W2h[E_DIM * F_DIM / 8];

__global__ void cvt_w2_kernel(const float* __restrict__ W2) {
    int i = blockIdx.x * 256 + threadIdx.x;          // float4 index, 262144 total
    float4 v = ((const float4*)W2)[i];
    __half2* o = (__half2*)g_W2h;
    o[2 * i]     = __floats2half2_rn(v.x, v.y);
    o[2 * i + 1] = __floats2half2_rn(v.z, v.w);
}

static __device__ __forceinline__ uint32_t cvta_smem(const void* p) {
    uint32_t a;
    asm("{ .reg .u64 t; cvta.to.shared.u64 t, %1; cvt.u32.u64 %0, t; }" : "=r"(a) : "l"(p));
    return a;
}

static __device__ __forceinline__ void sts128(uint32_t addr, uint32_t r0, uint32_t r1,
                                              uint32_t r2, uint32_t r3) {
    asm volatile("st.shared.v4.b32 [%0], {%1,%2,%3,%4};"
                 :: "r"(addr), "r"(r0), "r"(r1), "r"(r2), "r"(r3) : "memory");
}

static __device__ __forceinline__ void ldsm4(uint32_t* r, uint32_t a) {
    asm volatile("ldmatrix.sync.aligned.m8n8.x4.shared.b16 {%0,%1,%2,%3}, [%4];"
                 : "=r"(r[0]), "=r"(r[1]), "=r"(r[2]), "=r"(r[3]) : "r"(a));
}

static __device__ __forceinline__ void mma_f16(float* c, const uint32_t* a,
                                               uint32_t b0, uint32_t b1) {
    asm volatile(
        "mma.sync.aligned.m16n8k16.row.col.f32.f16.f16.f32 "
        "{%0,%1,%2,%3},{%4,%5,%6,%7},{%8,%9},{%0,%1,%2,%3};"
        : "+f"(c[0]), "+f"(c[1]), "+f"(c[2]), "+f"(c[3])
        : "r"(a[0]), "r"(a[1]), "r"(a[2]), "r"(a[3]), "r"(b0), "r"(b1));
}

// Producer: H rows (relu(q.W1) -> fp16, swizzled STS) + W2 chunk STS
static __device__ __forceinline__ void produce(
    int kkp, uint32_t nboff_a, uint32_t nboff_b,
    const float* __restrict__ w1s, const float* __restrict__ qme, int hh,
    uint32_t aRowAddr, uint32_t aC0, uint32_t aC1, uint32_t bAddr, uint4 w2v)
{
    float4 qa = ((const float4*)qme)[0];
    float4 qb = ((const float4*)qme)[1];
    uint32_t pk[8];
    const float* wbase = w1s + (size_t)(kkp + hh * 16) * 8;
    #pragma unroll
    for (int jj = 0; jj < 8; ++jj) {
        float s[2];
        #pragma unroll
        for (int u = 0; u < 2; ++u) {
            const float4* wv = (const float4*)(wbase + (jj * 2 + u) * 8);
            float4 wa = wv[0], wb = wv[1];
            float t = qa.x * wa.x;
            t = fmaf(qa.y, wa.y, t);
            t = fmaf(qa.z, wa.z, t);
            t = fmaf(qa.w, wa.w, t);
            t = fmaf(qb.x, wb.x, t);
            t = fmaf(qb.y, wb.y, t);
            t = fmaf(qb.z, wb.z, t);
            t = fmaf(qb.w, wb.w, t);
            s[u] = fmaxf(t, 0.0f);
        }
        __half2 hv = __floats2half2_rn(s[0], s[1]);
        pk[jj] = *(uint32_t*)&hv;
    }
    sts128(aRowAddr + nboff_a + aC0, pk[0], pk[1], pk[2], pk[3]);
    sts128(aRowAddr + nboff_a + aC1, pk[4], pk[5], pk[6], pk[7]);
    sts128(bAddr + nboff_b, w2v.x, w2v.y, w2v.z, w2v.w);
}

__global__ void __launch_bounds__(THREADS, 1)
ffq_kernel(const float* __restrict__ x,
           const float* __restrict__ theta,
           const float* __restrict__ W1,
           float* __restrict__ out)
{
    extern __shared__ char dsm[];
    const uint32_t raw = cvta_smem(dsm);
    const uint32_t sbase = (raw + 1023) & ~1023u;
    char* gb = dsm + (sbase - raw);

    const int tid  = threadIdx.x;
    const int warp = tid >> 5, lane = tid & 31;
    const int wm = warp >> 2, wn = warp & 3;
    const int mt = blockIdx.x >> 2, nt = blockIdx.x & 3;
    const int m0 = mt * BM, n0 = nt * BN;

    float* w1s = (float*)(gb + SW1);

    // ---- stage W1 (2048x8 fp32 = 64KB), coalesced ----
    #pragma unroll
    for (int i = 0; i < 8; ++i) {
        int idx4 = i * 512 + tid;
        ((float4*)w1s)[idx4] = ((const float4*)W1)[idx4];
    }

    // ---- q = cos(2*x[:, :8] + theta) into smem (one writer per row) ----
    const int hr = tid >> 1, hh = tid & 1;
    if (hh == 0) {
        const float* xr = x + (size_t)(m0 + hr) * E_DIM;
        float4 x0 = ((const float4*)xr)[0];
        float4 x1 = ((const float4*)xr)[1];
        float* qd = (float*)(gb + SQ) + hr * 8;
        qd[0] = cosf(2.0f * x0.x + __ldg(theta + 0));
        qd[1] = cosf(2.0f * x0.y + __ldg(theta + 1));
        qd[2] = cosf(2.0f * x0.z + __ldg(theta + 2));
        qd[3] = cosf(2.0f * x0.w + __ldg(theta + 3));
        qd[4] = cosf(2.0f * x1.x + __ldg(theta + 4));
        qd[5] = cosf(2.0f * x1.y + __ldg(theta + 5));
        qd[6] = cosf(2.0f * x1.z + __ldg(theta + 6));
        qd[7] = cosf(2.0f * x1.w + __ldg(theta + 7));
    }
    __syncthreads();

    // ---- producer constants ----
    const float* qme = (const float*)(gb + SQ) + hr * 8;
    const uint32_t aRowAddr = sbase + SA0 + hr * 64;
    const uint32_t aSw = (hr >> 1) & 3;
    const uint32_t aC0 = ((2u * hh) ^ aSw) << 4;
    const uint32_t aC1 = ((2u * hh + 1u) ^ aSw) << 4;
    const int bn_row = tid >> 2, bc = tid & 3;
    const uint32_t bAddr = sbase + SB0 + bn_row * 64 + ((bc ^ ((bn_row >> 1) & 3)) << 4);
    const uint4* w2base = g_W2h + (size_t)(n0 + bn_row) * 256 + bc;

    // ---- consumer constants ----
    const int t8 = lane >> 3, r8 = lane & 7;
    const int aCrow = wm * 64 + (t8 & 1) * 8 + r8;
    const uint32_t aCs = (aCrow >> 1) & 3;
    const uint32_t aCbase = sbase + SA0 + aCrow * 64;
    const int aCk = t8 >> 1;
    const int bCrow = wn * 32 + (t8 >> 1) * 8 + r8;
    const uint32_t bCs = (bCrow >> 1) & 3;
    const uint32_t bCbase = sbase + SB0 + bCrow * 64;
    const int bCk = t8 & 1;

    float acc[4][4][4];
    #pragma unroll
    for (int i = 0; i < 4; ++i)
        #pragma unroll
        for (int j = 0; j < 4; ++j)
            #pragma unroll
            for (int e = 0; e < 4; ++e) acc[i][j][e] = 0.0f;

    // ---- prologue: produce chunk 0 into buffer 0 ----
    {
        uint4 w2v = __ldg(w2base);
        produce(0, 0, 0, w1s, qme, hh, aRowAddr, aC0, aC1, bAddr, w2v);
    }
    __syncthreads();

    for (int it = 0; it < K_ITERS; ++it) {
        const int b = it & 1, nb = b ^ 1;
        const bool dp = (it + 1 < K_ITERS);
        const int kkn = (it + 1) * BK;

        uint4 w2v;
        if (dp) w2v = __ldg(w2base + (kkn >> 3));

        // ---- consume buffer b ----
        const uint32_t aoff = (uint32_t)b * SAB;
        const uint32_t boff = (uint32_t)b * SBB;
        #pragma unroll
        for (int ks = 0; ks < 2; ++ks) {
            uint32_t a[4][4];
            #pragma unroll
            for (int im = 0; im < 4; ++im)
                ldsm4(a[im], aCbase + aoff + im * 1024 + ((((uint32_t)(ks * 2 + aCk)) ^ aCs) << 4));
            uint32_t bb[2][4];
            #pragma unroll
            for (int jp = 0; jp < 2; ++jp)
                ldsm4(bb[jp], bCbase + boff + jp * 1024 + ((((uint32_t)(ks * 2 + bCk)) ^ bCs) << 4));
            #pragma unroll
            for (int im = 0; im < 4; ++im)
                #pragma unroll
                for (int jn = 0; jn < 4; ++jn)
                    mma_f16(acc[im][jn], a[im], bb[jn >> 1][(jn & 1) * 2], bb[jn >> 1][(jn & 1) * 2 + 1]);
        }

        // ---- produce chunk it+1 into buffer nb ----
        if (dp) {
            produce(kkn, (uint32_t)nb * SAB, (uint32_t)nb * SBB,
                    w1s, qme, hh, aRowAddr, aC0, aC1, bAddr, w2v);
        }
        __syncthreads();
    }

    // ---- epilogue: acc -> out ----
    const int g  = lane >> 2, tq = lane & 3;
    #pragma unroll
    for (int im = 0; im < 4; ++im) {
        const int row0 = m0 + wm * 64 + im * 16 + g;
        #pragma unroll
        for (int jn = 0; jn < 4; ++jn) {
            const int col = n0 + wn * 32 + jn * 8 + tq * 2;
            *(float2*)(out + (size_t)row0 * E_DIM + col) =
                make_float2(acc[im][jn][0], acc[im][jn][1]);
            *(float2*)(out + (size_t)(row0 + 8) * E_DIM + col) =
                make_float2(acc[im][jn][2], acc[im][jn][3]);
        }
    }
}

extern "C" void kernel_launch(void* const* d_in, const int* in_sizes, int n_in,
                              void* d_out, int out_size) {
    const float* x     = (const float*)d_in[0];
    const float* theta = (const float*)d_in[1];
    const float* W1    = (const float*)d_in[2];
    const float* W2    = (const float*)d_in[3];
    float* out = (float*)d_out;

    cvt_w2_kernel<<<(E_DIM * F_DIM / 4) / 256, 256>>>(W2);

    cudaFuncSetAttribute(ffq_kernel, cudaFuncAttributeMaxDynamicSharedMemorySize, SMEM_BYTES);
    dim3 grid((M_TOTAL / BM) * (E_DIM / BN));  // 128 * 4 = 512 CTAs
    ffq_kernel<<<grid, THREADS, SMEM_BYTES>>>(x, theta, W1, out);
}

// round 6
// speedup vs baseline: 1.7860x; 1.6836x over previous
#include <cuda_runtime.h>
#include <cuda_fp16.h>
#include <math.h>
#include <stdint.h>

#define M_TOTAL 32768
#define E_DIM   512
#define F_DIM   2048

#define BM 128
#define BN 256
#define BK 32
#define THREADS 256
#define K_ITERS 64

// smem offsets (relative to 1024-aligned base)
#define SQ   0           // q fp32 [128][8] = 4096
#define SA0  4096        // A (H fp16) [128 rows][64B] dbl: 2 x 8192
#define SAB  8192
#define SB0  20480       // B (W2 fp16) [256 rows][64B] dbl: 2 x 16384
#define SBB  16384
#define SMEM_BYTES (53248 + 1024)

// fp16 copy of W2 (E x F), row-major [n][k], uint4 = 8 halves
__device__ uint4 g_W2h[E_DIM * F_DIM / 8];

__global__ void cvt_w2_kernel(const float* __restrict__ W2) {
    int i = blockIdx.x * 256 + threadIdx.x;
    float4 v = ((const float4*)W2)[i];
    __half2* o = (__half2*)g_W2h;
    o[2 * i]     = __floats2half2_rn(v.x, v.y);
    o[2 * i + 1] = __floats2half2_rn(v.z, v.w);
}

static __device__ __forceinline__ uint32_t cvta_smem(const void* p) {
    uint32_t a;
    asm("{ .reg .u64 t; cvta.to.shared.u64 t, %1; cvt.u32.u64 %0, t; }" : "=r"(a) : "l"(p));
    return a;
}

static __device__ __forceinline__ void sts128(uint32_t addr, uint32_t r0, uint32_t r1,
                                              uint32_t r2, uint32_t r3) {
    asm volatile("st.shared.v4.b32 [%0], {%1,%2,%3,%4};"
                 :: "r"(addr), "r"(r0), "r"(r1), "r"(r2), "r"(r3) : "memory");
}

static __device__ __forceinline__ void ldsm4(uint32_t* r, uint32_t a) {
    asm volatile("ldmatrix.sync.aligned.m8n8.x4.shared.b16 {%0,%1,%2,%3}, [%4];"
                 : "=r"(r[0]), "=r"(r[1]), "=r"(r[2]), "=r"(r[3]) : "r"(a));
}

static __device__ __forceinline__ void mma_f16(float* c, const uint32_t* a,
                                               uint32_t b0, uint32_t b1) {
    asm volatile(
        "mma.sync.aligned.m16n8k16.row.col.f32.f16.f16.f32 "
        "{%0,%1,%2,%3},{%4,%5,%6,%7},{%8,%9},{%0,%1,%2,%3};"
        : "+f"(c[0]), "+f"(c[1]), "+f"(c[2]), "+f"(c[3])
        : "r"(a[0]), "r"(a[1]), "r"(a[2]), "r"(a[3]), "r"(b0), "r"(b1));
}

static __device__ __forceinline__ float dot8(const float4& qa, const float4& qb,
                                             const float4& wa, const float4& wb) {
    float t = qa.x * wa.x;
    t = fmaf(qa.y, wa.y, t);
    t = fmaf(qa.z, wa.z, t);
    t = fmaf(qa.w, wa.w, t);
    t = fmaf(qb.x, wb.x, t);
    t = fmaf(qb.y, wb.y, t);
    t = fmaf(qb.z, wb.z, t);
    t = fmaf(qb.w, wb.w, t);
    return t;
}

__global__ void __launch_bounds__(THREADS, 1)
ffq_kernel(const float* __restrict__ x,
           const float* __restrict__ theta,
           const float* __restrict__ W1,
           float* __restrict__ out)
{
    extern __shared__ char dsm[];
    const uint32_t raw = cvta_smem(dsm);
    const uint32_t sbase = (raw + 1023) & ~1023u;
    char* gb = dsm + (sbase - raw);

    const int tid  = threadIdx.x;
    const int warp = tid >> 5, lane = tid & 31;
    const int wm = warp >> 2, wn = warp & 3;       // consumer: 2 x 4 warp grid, tile 64x64
    const int mt = blockIdx.x >> 1, nt = blockIdx.x & 1;
    const int m0 = mt * BM, n0 = nt * BN;

    // ---- q = cos(2*x[:, :8] + theta) into smem (rows 0..127) ----
    if (tid < BM) {
        const float* xr = x + (size_t)(m0 + tid) * E_DIM;
        float4 x0 = ((const float4*)xr)[0];
        float4 x1 = ((const float4*)xr)[1];
        float* qd = (float*)(gb + SQ) + tid * 8;
        qd[0] = cosf(2.0f * x0.x + __ldg(theta + 0));
        qd[1] = cosf(2.0f * x0.y + __ldg(theta + 1));
        qd[2] = cosf(2.0f * x0.z + __ldg(theta + 2));
        qd[3] = cosf(2.0f * x0.w + __ldg(theta + 3));
        qd[4] = cosf(2.0f * x1.x + __ldg(theta + 4));
        qd[5] = cosf(2.0f * x1.y + __ldg(theta + 5));
        qd[6] = cosf(2.0f * x1.z + __ldg(theta + 6));
        qd[7] = cosf(2.0f * x1.w + __ldg(theta + 7));
    }
    __syncthreads();

    // ---- producer constants ----
    // A producer: kq warp-uniform; thread handles rows rp and rp+64, k in [8*kq, 8*kq+8)
    const int kq = warp & 3;
    const int rp = ((warp >> 2) << 5) + lane;       // 0..63
    const int r1 = rp + 64;
    float4 qa0, qa1, qb0, qb1;
    {
        const float* qp = (const float*)(gb + SQ);
        qa0 = ((const float4*)(qp + rp * 8))[0];
        qa1 = ((const float4*)(qp + rp * 8))[1];
        qb0 = ((const float4*)(qp + r1 * 8))[0];
        qb1 = ((const float4*)(qp + r1 * 8))[1];
    }
    const uint32_t aAddr0 = sbase + SA0 + rp * 64 + (((uint32_t)kq ^ ((rp >> 1) & 3)) << 4);
    const uint32_t aAddr1 = sbase + SA0 + r1 * 64 + (((uint32_t)kq ^ ((r1 >> 1) & 3)) << 4);
    // B producer: thread handles rows (p*64 + tid>>2), 16B column c = tid&3
    const int bnr = tid >> 2, bc = tid & 3;

    // ---- consumer constants ----
    const int t8 = lane >> 3, r8 = lane & 7;
    const int aCrow = wm * 64 + (t8 & 1) * 8 + r8;
    const uint32_t aCs = (aCrow >> 1) & 3;
    const uint32_t aCbase = sbase + SA0 + aCrow * 64;
    const int aCk = t8 >> 1;
    const int bCrow = wn * 64 + (t8 >> 1) * 8 + r8;
    const uint32_t bCs = (bCrow >> 1) & 3;
    const uint32_t bCbase = sbase + SB0 + bCrow * 64;
    const int bCk = t8 & 1;

    float acc[4][8][4];
    #pragma unroll
    for (int i = 0; i < 4; ++i)
        #pragma unroll
        for (int j = 0; j < 8; ++j)
            #pragma unroll
            for (int e = 0; e < 4; ++e) acc[i][j][e] = 0.0f;

    // ---- prologue: produce chunk 0 into buffer 0 ----
    {
        // B tile chunk 0
        #pragma unroll
        for (int p = 0; p < 4; ++p) {
            int n = p * 64 + bnr;
            uint4 v = __ldg(g_W2h + (size_t)(n0 + n) * 256 + bc);
            uint32_t ad = sbase + SB0 + n * 64 + (((uint32_t)bc ^ ((n >> 1) & 3)) << 4);
            sts128(ad, v.x, v.y, v.z, v.w);
        }
        // A tile chunk 0
        const float* wrow = W1 + (size_t)(kq * 8) * 8;
        uint32_t pk0[4], pk1[4];
        #pragma unroll
        for (int jp = 0; jp < 4; ++jp) {
            float s0a, s1a, s0b, s1b;
            {
                float4 wa = ((const float4*)(wrow + (jp * 2) * 8))[0];
                float4 wb = ((const float4*)(wrow + (jp * 2) * 8))[1];
                s0a = fmaxf(dot8(qa0, qa1, wa, wb), 0.0f);
                s1a = fmaxf(dot8(qb0, qb1, wa, wb), 0.0f);
            }
            {
                float4 wa = ((const float4*)(wrow + (jp * 2 + 1) * 8))[0];
                float4 wb = ((const float4*)(wrow + (jp * 2 + 1) * 8))[1];
                s0b = fmaxf(dot8(qa0, qa1, wa, wb), 0.0f);
                s1b = fmaxf(dot8(qb0, qb1, wa, wb), 0.0f);
            }
            __half2 h0 = __floats2half2_rn(s0a, s0b);
            __half2 h1 = __floats2half2_rn(s1a, s1b);
            pk0[jp] = *(uint32_t*)&h0;
            pk1[jp] = *(uint32_t*)&h1;
        }
        sts128(aAddr0, pk0[0], pk0[1], pk0[2], pk0[3]);
        sts128(aAddr1, pk1[0], pk1[1], pk1[2], pk1[3]);
    }
    __syncthreads();

    for (int it = 0; it < K_ITERS; ++it) {
        const int b = it & 1, nb = b ^ 1;
        const bool dp = (it + 1 < K_ITERS);
        const int kkn = (it + 1) * BK;

        // prefetch next B chunk from gmem (L2-resident W2h)
        uint4 w2v[4];
        if (dp) {
            #pragma unroll
            for (int p = 0; p < 4; ++p) {
                int n = p * 64 + bnr;
                w2v[p] = __ldg(g_W2h + (size_t)(n0 + n) * 256 + (kkn >> 3) + bc);
            }
        }

        // ---- consume buffer b ----
        const uint32_t aoff = (uint32_t)b * SAB;
        const uint32_t boff = (uint32_t)b * SBB;
        #pragma unroll
        for (int ks = 0; ks < 2; ++ks) {
            uint32_t a[4][4];
            #pragma unroll
            for (int im = 0; im < 4; ++im)
                ldsm4(a[im], aCbase + aoff + im * 1024 +
                             ((((uint32_t)(ks * 2 + aCk)) ^ aCs) << 4));
            uint32_t bb[4][4];
            #pragma unroll
            for (int jp = 0; jp < 4; ++jp)
                ldsm4(bb[jp], bCbase + boff + jp * 1024 +
                              ((((uint32_t)(ks * 2 + bCk)) ^ bCs) << 4));
            #pragma unroll
            for (int im = 0; im < 4; ++im)
                #pragma unroll
                for (int jn = 0; jn < 8; ++jn)
                    mma_f16(acc[im][jn], a[im],
                            bb[jn >> 1][(jn & 1) * 2], bb[jn >> 1][(jn & 1) * 2 + 1]);
        }

        // ---- produce chunk it+1 into buffer nb ----
        if (dp) {
            #pragma unroll
            for (int p = 0; p < 4; ++p) {
                int n = p * 64 + bnr;
                uint32_t ad = sbase + SB0 + (uint32_t)nb * SBB + n * 64 +
                              (((uint32_t)bc ^ ((n >> 1) & 3)) << 4);
                sts128(ad, w2v[p].x, w2v[p].y, w2v[p].z, w2v[p].w);
            }
            const float* wrow = W1 + (size_t)(kkn + kq * 8) * 8;
            uint32_t pk0[4], pk1[4];
            #pragma unroll
            for (int jp = 0; jp < 4; ++jp) {
                float s0a, s1a, s0b, s1b;
                {
                    float4 wa = ((const float4*)(wrow + (jp * 2) * 8))[0];
                    float4 wb = ((const float4*)(wrow + (jp * 2) * 8))[1];
                    s0a = fmaxf(dot8(qa0, qa1, wa, wb), 0.0f);
                    s1a = fmaxf(dot8(qb0, qb1, wa, wb), 0.0f);
                }
                {
                    float4 wa = ((const float4*)(wrow + (jp * 2 + 1) * 8))[0];
                    float4 wb = ((const float4*)(wrow + (jp * 2 + 1) * 8))[1];
                    s0b = fmaxf(dot8(qa0, qa1, wa, wb), 0.0f);
                    s1b = fmaxf(dot8(qb0, qb1, wa, wb), 0.0f);
                }
                __half2 h0 = __floats2half2_rn(s0a, s0b);
                __half2 h1 = __floats2half2_rn(s1a, s1b);
                pk0[jp] = *(uint32_t*)&h0;
                pk1[jp] = *(uint32_t*)&h1;
            }
            sts128(aAddr0 + (uint32_t)nb * SAB, pk0[0], pk0[1], pk0[2], pk0[3]);
            sts128(aAddr1 + (uint32_t)nb * SAB, pk1[0], pk1[1], pk1[2], pk1[3]);
        }
        __syncthreads();
    }

    // ---- epilogue: acc -> out ----
    const int g = lane >> 2, tq = lane & 3;
    #pragma unroll
    for (int im = 0; im < 4; ++im) {
        const int row0 = m0 + wm * 64 + im * 16 + g;
        #pragma unroll
        for (int jn = 0; jn < 8; ++jn) {
            const int col = n0 + wn * 64 + jn * 8 + tq * 2;
            *(float2*)(out + (size_t)row0 * E_DIM + col) =
                make_float2(acc[im][jn][0], acc[im][jn][1]);
            *(float2*)(out + (size_t)(row0 + 8) * E_DIM + col) =
                make_float2(acc[im][jn][2], acc[im][jn][3]);
        }
    }
}

extern "C" void kernel_launch(void* const* d_in, const int* in_sizes, int n_in,
                              void* d_out, int out_size) {
    const float* x     = (const float*)d_in[0];
    const float* theta = (const float*)d_in[1];
    const float* W1    = (const float*)d_in[2];
    const float* W2    = (const float*)d_in[3];
    float* out = (float*)d_out;

    cvt_w2_kernel<<<(E_DIM * F_DIM / 4) / 256, 256>>>(W2);

    cudaFuncSetAttribute(ffq_kernel, cudaFuncAttributeMaxDynamicSharedMemorySize, SMEM_BYTES);
    dim3 grid((M_TOTAL / BM) * (E_DIM / BN));  // 256 * 2 = 512 CTAs
    ffq_kernel<<<grid, THREADS, SMEM_BYTES>>>(x, theta, W1, out);
}